// round 5
// baseline (speedup 1.0000x reference)
#include <cuda_runtime.h>
#include <cstdint>

// Problem constants (fixed shapes per reference setup_inputs)
#define S 8192      // tokens
#define M 2048      // model dim
#define E 64        // experts
#define CAP 256     // capacity = TOP_K * ceil(S/E) = 2 * 128
#define KSPLIT 2
#define KCHUNK (M / KSPLIT)   // 1024
#define BK 16
#define BM 64                 // tokens per gemm block
#define NMB (S / BM)          // 128 token-blocks
#define NG (NMB * KSPLIT)     // 256 gemm blocks
#define FILL_F4_PER_BLOCK 8192

typedef unsigned long long ull;

// ---- device scratch (no allocations allowed) ----
__device__ float g_part[KSPLIT][S][E];  // 4 MB partial logits
__device__ int   g_expert[S];
__device__ float g_gate[S];

__device__ __forceinline__ ull dup2(float x) {
    ull r; asm("mov.b64 %0, {%1, %1};" : "=l"(r) : "f"(x)); return r;
}
__device__ __forceinline__ void ffma2(ull &acc, ull a, ull b) {
    asm("fma.rn.f32x2 %0, %1, %2, %0;" : "+l"(acc) : "l"(a), "l"(b));
}
__device__ __forceinline__ float2 unpack2(ull v) {
    float2 f; asm("mov.b64 {%0, %1}, %2;" : "=f"(f.x), "=f"(f.y) : "l"(v));
    return f;
}

// ============================================================
// Kernel 1 (fused): blocks [0, NG) compute partial logits GEMM
// with packed f32x2 FMA (small 16-reg accumulator tile to keep
// occupancy high for the fill blocks); blocks [NG, ...) stream
// float4 zeros over the output. Structural overlap: fill
// saturates DRAM while gemm uses the fma pipes.
// ============================================================
__global__ void __launch_bounds__(256, 6) fused_kernel(const float* __restrict__ A,
                                                       const float* __restrict__ B,
                                                       float4* __restrict__ out,
                                                       int nf4) {
    const int bx = blockIdx.x;
    if (bx >= NG) {
        // ---------------- fill branch ----------------
        const int fb = bx - NG;
        int idx = fb * FILL_F4_PER_BLOCK + threadIdx.x;
        const float4 z = make_float4(0.f, 0.f, 0.f, 0.f);
        #pragma unroll
        for (int i = 0; i < FILL_F4_PER_BLOCK / 256; i++) {
            if (idx < nf4) out[idx] = z;
            idx += 256;
        }
        return;
    }

    // ---------------- gemm branch ----------------
    // Block tile: 64 tokens x 64 experts; thread tile 4 tokens x 4 experts.
    __shared__ __align__(16) float As[BK][BM];        // [k][token]
    __shared__ __align__(16) ull   Bs[2][BK][32];     // [plane][k][slot], dup'd {b,b}

    const int tid = threadIdx.x;
    const int mb  = bx & (NMB - 1);   // token-block
    const int ks  = bx >> 7;          // k-split index
    const int tokBase = mb * BM;
    const int kb0 = ks * KCHUNK;

    // A loader: 64 tokens x 16 k = 256 float4; token = tid&63, kq = tid>>6
    const int atok = tid & 63;
    const int akq  = tid >> 6;        // 0..3
    const float* arow = A + (size_t)(tokBase + atok) * M + kb0 + akq * 4;

    // B loader: expert = tid>>2, k-quad = tid&3
    const int be = tid >> 2;
    const int bj = tid & 3;
    const float* brow = B + (size_t)be * M + kb0 + bj * 4;
    const int bp   = (be >> 1) & 1;             // plane
    const int bslt = (be >> 2) * 2 + (be & 1);  // ull slot within row

    // compute roles: 4 tokens (2 packed pairs) x 4 experts
    const int tt = tid >> 4;          // 0..15
    const int te = tid & 15;          // 0..15

    ull acc[2][4];
    #pragma unroll
    for (int p = 0; p < 2; p++)
        #pragma unroll
        for (int j = 0; j < 4; j++) acc[p][j] = 0ull;

    for (int tile = 0; tile < KCHUNK / BK; tile++) {
        const int kb = tile * BK;
        float4 av = *(const float4*)(arow + kb);
        float4 bv = *(const float4*)(brow + kb);

        __syncthreads();  // previous compute done before overwrite

        As[akq*4 + 0][atok] = av.x;  As[akq*4 + 1][atok] = av.y;
        As[akq*4 + 2][atok] = av.z;  As[akq*4 + 3][atok] = av.w;

        Bs[bp][bj*4 + 0][bslt] = dup2(bv.x);
        Bs[bp][bj*4 + 1][bslt] = dup2(bv.y);
        Bs[bp][bj*4 + 2][bslt] = dup2(bv.z);
        Bs[bp][bj*4 + 3][bslt] = dup2(bv.w);

        __syncthreads();

        #pragma unroll
        for (int kk = 0; kk < BK; kk++) {
            ulonglong2 a = *(const ulonglong2*)&As[kk][tt * 4];   // {t0,t1},{t2,t3}
            ulonglong2 b0 = ((const ulonglong2*)&Bs[0][kk][0])[te]; // e0,e1
            ulonglong2 b1 = ((const ulonglong2*)&Bs[1][kk][0])[te]; // e2,e3
            ffma2(acc[0][0], a.x, b0.x);
            ffma2(acc[0][1], a.x, b0.y);
            ffma2(acc[0][2], a.x, b1.x);
            ffma2(acc[0][3], a.x, b1.y);
            ffma2(acc[1][0], a.y, b0.x);
            ffma2(acc[1][1], a.y, b0.y);
            ffma2(acc[1][2], a.y, b1.x);
            ffma2(acc[1][3], a.y, b1.y);
        }
    }

    // Write partials: token rows tokBase + tt*4 + 2p (+1), experts te*4..+3
    #pragma unroll
    for (int p = 0; p < 2; p++) {
        float2 v0 = unpack2(acc[p][0]);
        float2 v1 = unpack2(acc[p][1]);
        float2 v2 = unpack2(acc[p][2]);
        float2 v3 = unpack2(acc[p][3]);
        int r0 = tokBase + tt * 4 + 2 * p;
        *(float4*)&g_part[ks][r0    ][te * 4] = make_float4(v0.x, v1.x, v2.x, v3.x);
        *(float4*)&g_part[ks][r0 + 1][te * 4] = make_float4(v0.y, v1.y, v2.y, v3.y);
    }
}

// ============================================================
// Kernel 2: reduce KSPLIT partials, per-token softmax + argmax.
// One warp per token; lane covers experts {lane, lane+32}.
// Tie-break: lowest expert index (matches jnp.argmax).
// ============================================================
__global__ void __launch_bounds__(256) softargmax_kernel() {
    int gw   = (blockIdx.x * blockDim.x + threadIdx.x) >> 5;
    int lane = threadIdx.x & 31;
    if (gw >= S) return;

    float v0 = 0.f, v1 = 0.f;
    #pragma unroll
    for (int ks = 0; ks < KSPLIT; ks++) {
        v0 += g_part[ks][gw][lane];
        v1 += g_part[ks][gw][lane + 32];
    }

    float bv; int bi;
    if (v0 >= v1) { bv = v0; bi = lane; }
    else          { bv = v1; bi = lane + 32; }

    #pragma unroll
    for (int off = 16; off; off >>= 1) {
        float ov = __shfl_xor_sync(0xffffffffu, bv, off);
        int   oi = __shfl_xor_sync(0xffffffffu, bi, off);
        if (ov > bv || (ov == bv && oi < bi)) { bv = ov; bi = oi; }
    }

    float ssum = expf(v0 - bv) + expf(v1 - bv);
    #pragma unroll
    for (int off = 16; off; off >>= 1)
        ssum += __shfl_xor_sync(0xffffffffu, ssum, off);

    if (lane == 0) {
        g_expert[gw] = bi;
        g_gate[gw]   = 1.0f / ssum;
    }
}

// ============================================================
// Kernel 3: fused capacity-rank + scatter. One block per expert:
// stable prefix scan over token order; tokens with rank < CAP
// write their gate (and mask 1.0) directly into the zeroed out.
// ============================================================
__global__ void __launch_bounds__(256) rank_scatter_kernel(float* __restrict__ out, int two) {
    const int e = blockIdx.x;
    __shared__ int warp_sums[8];
    int running = 0;
    const int lane = threadIdx.x & 31;
    const int warp = threadIdx.x >> 5;

    for (int base = 0; base < S; base += 256) {
        int s = base + threadIdx.x;
        int flag = (g_expert[s] == e) ? 1 : 0;
        unsigned bits = __ballot_sync(0xffffffffu, flag);
        int excl = __popc(bits & ((1u << lane) - 1u));
        if (lane == 0) warp_sums[warp] = __popc(bits);
        __syncthreads();
        int woff = 0, tot = 0;
        #pragma unroll
        for (int w = 0; w < 8; w++) {
            int ws = warp_sums[w];
            if (w < warp) woff += ws;
            tot += ws;
        }
        int pos = running + woff + excl;
        if (flag && pos < CAP) {
            size_t off = (size_t)s * (E * CAP) + (size_t)e * CAP + (size_t)pos;
            out[off] = g_gate[s];
            if (two) out[(size_t)S * E * CAP + off] = 1.0f;
        }
        running += tot;
        __syncthreads();
    }
}

// ============================================================
extern "C" void kernel_launch(void* const* d_in, const int* in_sizes, int n_in,
                              void* d_out, int out_size) {
    const float* inp = (const float*)d_in[0];   // [S, M]
    const float* wg  = (const float*)d_in[1];   // [E, M]
    float* out = (float*)d_out;

    const long long SEC = (long long)S * E * CAP;
    const int two = ((long long)out_size >= 2 * SEC) ? 1 : 0;

    const int nf4   = out_size / 4;
    const int nfill = (nf4 + FILL_F4_PER_BLOCK - 1) / FILL_F4_PER_BLOCK;

    fused_kernel<<<NG + nfill, 256>>>(inp, wg, (float4*)out, nf4);
    softargmax_kernel<<<(S * 32) / 256, 256>>>();
    rank_scatter_kernel<<<E, 256>>>(out, two);
}

// round 6
// speedup vs baseline: 1.7243x; 1.7243x over previous
#include <cuda_runtime.h>
#include <cstdint>

// Problem constants (fixed shapes per reference setup_inputs)
#define S 8192      // tokens
#define M 2048      // model dim
#define E 64        // experts
#define CAP 256     // capacity = TOP_K * ceil(S/E) = 2 * 128
#define KSPLIT 4
#define KCHUNK (M / KSPLIT)   // 512
#define BK 16
#define BM 128                // tokens per gemm block
#define NMB (S / BM)          // 64 token-blocks
#define NG (NMB * KSPLIT)     // 256 gemm blocks
#define NT (KCHUNK / BK)      // 32 k-tiles
#define FILL_F4_PER_BLOCK 8192

typedef unsigned long long ull;

// ---- device scratch (no allocations allowed) ----
__device__ float g_part[KSPLIT][S][E];  // 8 MB partial logits
__device__ int   g_expert[S];
__device__ float g_gate[S];
__device__ int   g_cnt[3];              // [0]=gemm, [1]=soft, [2]=fill

__device__ __forceinline__ ull dup2(float x) {
    ull r; asm("mov.b64 %0, {%1, %1};" : "=l"(r) : "f"(x)); return r;
}
__device__ __forceinline__ void ffma2(ull &acc, ull a, ull b) {
    asm("fma.rn.f32x2 %0, %1, %2, %0;" : "+l"(acc) : "l"(a), "l"(b));
}
__device__ __forceinline__ float2 unpack2(ull v) {
    float2 f; asm("mov.b64 {%0, %1}, %2;" : "=f"(f.x), "=f"(f.y) : "l"(v));
    return f;
}

__global__ void init_kernel() {
    g_cnt[0] = 0; g_cnt[1] = 0; g_cnt[2] = 0;
}

// Release: all block stores visible, then bump counter.
__device__ __forceinline__ void block_signal(int idx) {
    __syncthreads();
    __threadfence();
    if (threadIdx.x == 0) atomicAdd(&g_cnt[idx], 1);
}
// Acquire: spin until counter reaches target.
__device__ __forceinline__ void block_wait(int idx, int target) {
    if (threadIdx.x == 0) {
        volatile int* c = &g_cnt[idx];
        while (*c < target) __nanosleep(128);
    }
    __syncthreads();
}

// ============================================================
// Fused pipeline kernel. Grid layout (index order = dispatch order):
//   [0, NG)                 : GEMM blocks (ks==0 blocks continue as softargmax)
//   [NG, NG+nfill)          : zero-fill blocks (bulk DRAM stream)
//   [NG+nfill, NG+nfill+E)  : rank+scatter blocks (spin on soft+fill done)
// ============================================================
__global__ void __launch_bounds__(256, 3) fused_kernel(const float* __restrict__ A,
                                                       const float* __restrict__ B,
                                                       float4* __restrict__ out4,
                                                       float* __restrict__ outF,
                                                       int nf4, int nfill, int two) {
    const int bx  = blockIdx.x;
    const int tid = threadIdx.x;

    if (bx >= NG) {
        if (bx < NG + nfill) {
            // ---------------- fill branch ----------------
            const int fb = bx - NG;
            int idx = fb * FILL_F4_PER_BLOCK + tid;
            const float4 z = make_float4(0.f, 0.f, 0.f, 0.f);
            #pragma unroll 8
            for (int i = 0; i < FILL_F4_PER_BLOCK / 256; i++) {
                if (idx < nf4) __stcs(&out4[idx], z);
                idx += 256;
            }
            block_signal(2);
            return;
        }
        // ---------------- rank + scatter branch ----------------
        block_wait(1, NMB);    // softargmax complete
        block_wait(2, nfill);  // output fully zeroed
        const int e = bx - NG - nfill;
        __shared__ int warp_sums[8];
        int running = 0;
        const int lane = tid & 31;
        const int warp = tid >> 5;
        for (int base = 0; base < S; base += 256) {
            int s = base + tid;
            int flag = (g_expert[s] == e) ? 1 : 0;
            unsigned bits = __ballot_sync(0xffffffffu, flag);
            int excl = __popc(bits & ((1u << lane) - 1u));
            if (lane == 0) warp_sums[warp] = __popc(bits);
            __syncthreads();
            int woff = 0, tot = 0;
            #pragma unroll
            for (int w = 0; w < 8; w++) {
                int ws = warp_sums[w];
                if (w < warp) woff += ws;
                tot += ws;
            }
            int pos = running + woff + excl;
            if (flag && pos < CAP) {
                size_t off = (size_t)s * (E * CAP) + (size_t)e * CAP + (size_t)pos;
                outF[off] = g_gate[s];
                if (two) outF[(size_t)S * E * CAP + off] = 1.0f;
            }
            running += tot;
            __syncthreads();
        }
        return;
    }

    // ---------------- gemm branch (R4 shape: 128x64 block, 8x4 thread tile) ----------------
    __shared__ __align__(16) float As[BK][BM];        // [k][token]
    __shared__ __align__(16) ull   Bs[2][BK][32];     // [plane][k][slot], dup'd {b,b}

    const int mb  = bx & (NMB - 1);   // token-block
    const int ks  = bx >> 6;          // k-split index
    const int tokBase = mb * BM;
    const int kb0 = ks * KCHUNK;

    // A loader: token = tid&127, k-quads (tid>>7) and (tid>>7)+2
    const int atok = tid & 127;
    const int akq  = tid >> 7;        // 0 or 1
    const float* arow = A + (size_t)(tokBase + atok) * M + kb0;

    // B loader: expert = tid>>2, k-quad = tid&3
    const int be = tid >> 2;
    const int bj = tid & 3;
    const float* brow = B + (size_t)be * M + kb0 + bj * 4;
    const int bp   = (be >> 1) & 1;             // plane
    const int bslt = (be >> 2) * 2 + (be & 1);  // ull slot within row

    // compute roles: 8 tokens (4 packed pairs) x 4 experts
    const int tt = tid >> 4;          // 0..15
    const int te = tid & 15;          // 0..15

    ull acc[4][4];
    #pragma unroll
    for (int p = 0; p < 4; p++)
        #pragma unroll
        for (int j = 0; j < 4; j++) acc[p][j] = 0ull;

    // register-prefetch double buffering
    float4 a0 = *(const float4*)(arow + akq * 4);
    float4 a1 = *(const float4*)(arow + akq * 4 + 8);
    float4 bv = *(const float4*)(brow);

    for (int tile = 0; tile < NT; tile++) {
        __syncthreads();  // previous compute done before overwrite

        As[akq*4 + 0][atok] = a0.x;  As[akq*4 + 1][atok] = a0.y;
        As[akq*4 + 2][atok] = a0.z;  As[akq*4 + 3][atok] = a0.w;
        As[akq*4 + 8][atok] = a1.x;  As[akq*4 + 9][atok] = a1.y;
        As[akq*4 +10][atok] = a1.z;  As[akq*4 +11][atok] = a1.w;

        Bs[bp][bj*4 + 0][bslt] = dup2(bv.x);
        Bs[bp][bj*4 + 1][bslt] = dup2(bv.y);
        Bs[bp][bj*4 + 2][bslt] = dup2(bv.z);
        Bs[bp][bj*4 + 3][bslt] = dup2(bv.w);

        __syncthreads();

        if (tile + 1 < NT) {  // prefetch next tile while computing
            const int kb = (tile + 1) * BK;
            a0 = *(const float4*)(arow + kb + akq * 4);
            a1 = *(const float4*)(arow + kb + akq * 4 + 8);
            bv = *(const float4*)(brow + kb);
        }

        #pragma unroll
        for (int kk = 0; kk < BK; kk++) {
            const ulonglong2* ar = (const ulonglong2*)&As[kk][tt * 8];
            ulonglong2 a01 = ar[0];   // {t0,t1},{t2,t3}
            ulonglong2 a23 = ar[1];   // {t4,t5},{t6,t7}
            ulonglong2 b0 = ((const ulonglong2*)&Bs[0][kk][0])[te]; // e0,e1
            ulonglong2 b1 = ((const ulonglong2*)&Bs[1][kk][0])[te]; // e2,e3
            ull ap[4] = { a01.x, a01.y, a23.x, a23.y };
            #pragma unroll
            for (int p = 0; p < 4; p++) {
                ffma2(acc[p][0], ap[p], b0.x);
                ffma2(acc[p][1], ap[p], b0.y);
                ffma2(acc[p][2], ap[p], b1.x);
                ffma2(acc[p][3], ap[p], b1.y);
            }
        }
    }

    // Write partials: token rows tokBase + tt*8 + 2p (+1), experts te*4..+3
    #pragma unroll
    for (int p = 0; p < 4; p++) {
        float2 v0 = unpack2(acc[p][0]);
        float2 v1 = unpack2(acc[p][1]);
        float2 v2 = unpack2(acc[p][2]);
        float2 v3 = unpack2(acc[p][3]);
        int r0 = tokBase + tt * 8 + 2 * p;
        *(float4*)&g_part[ks][r0    ][te * 4] = make_float4(v0.x, v1.x, v2.x, v3.x);
        *(float4*)&g_part[ks][r0 + 1][te * 4] = make_float4(v0.y, v1.y, v2.y, v3.y);
    }

    block_signal(0);

    // ks==0 blocks continue as softargmax workers for their 128 tokens.
    if (ks == 0) {
        block_wait(0, NG);  // all partials visible

        const int warp = tid >> 5;
        const int lane = tid & 31;
        #pragma unroll 2
        for (int i = 0; i < 16; i++) {
            int t = tokBase + warp * 16 + i;
            float v0 = 0.f, v1 = 0.f;
            #pragma unroll
            for (int k = 0; k < KSPLIT; k++) {
                v0 += g_part[k][t][lane];
                v1 += g_part[k][t][lane + 32];
            }
            float bvv; int bi;
            if (v0 >= v1) { bvv = v0; bi = lane; }
            else          { bvv = v1; bi = lane + 32; }
            #pragma unroll
            for (int off = 16; off; off >>= 1) {
                float ov = __shfl_xor_sync(0xffffffffu, bvv, off);
                int   oi = __shfl_xor_sync(0xffffffffu, bi, off);
                if (ov > bvv || (ov == bvv && oi < bi)) { bvv = ov; bi = oi; }
            }
            float ssum = expf(v0 - bvv) + expf(v1 - bvv);
            #pragma unroll
            for (int off = 16; off; off >>= 1)
                ssum += __shfl_xor_sync(0xffffffffu, ssum, off);
            if (lane == 0) {
                g_expert[t] = bi;
                g_gate[t]   = 1.0f / ssum;
            }
        }
        block_signal(1);
    }
}

// ============================================================
extern "C" void kernel_launch(void* const* d_in, const int* in_sizes, int n_in,
                              void* d_out, int out_size) {
    const float* inp = (const float*)d_in[0];   // [S, M]
    const float* wg  = (const float*)d_in[1];   // [E, M]
    float* out = (float*)d_out;

    const long long SEC = (long long)S * E * CAP;
    const int two = ((long long)out_size >= 2 * SEC) ? 1 : 0;

    const int nf4   = out_size / 4;
    const int nfill = (nf4 + FILL_F4_PER_BLOCK - 1) / FILL_F4_PER_BLOCK;

    init_kernel<<<1, 1>>>();
    fused_kernel<<<NG + nfill + E, 256>>>(inp, wg, (float4*)out, out, nf4, nfill, two);
}